// round 16
// baseline (speedup 1.0000x reference)
#include <cuda_runtime.h>
#include <cuda_fp16.h>
#include <cstdint>
#include <cstddef>

#define DI __device__ __forceinline__

// ---------------- problem constants ----------------
constexpr int KDIM  = 2048;           // K == N for every GEMM
constexpr int BM = 64, BN = 128, BK = 32;
constexpr int NK = KDIM / BK;         // 64 k-chunks
constexpr int STAGES = 6;             // 6-stage ring, refilled 2 chunks per sync
constexpr uint32_t APLANE = BM * 64u;                 // 4096 B
constexpr uint32_t BPLANE = BN * 64u;                 // 8192 B
constexpr uint32_t STAGE_BYTES = APLANE + BPLANE;     // 12288
constexpr uint32_t SMEM_DYN = STAGES * STAGE_BYTES + 128;   // ~72KB -> 2 CTAs/SM

// ---------------- plane pool (all tensors single fp16 plane) ----------------
constexpr size_t MEG = 1024ull * 1024ull;
constexpr size_t OFF_X  = 0;          // fp16(concat(x0,x1)) [4096 x 2048]
constexpr size_t OFF_A0 = 8 * MEG;    // fp16(W0) row-major  [2048 x 2048]
constexpr size_t OFF_B1 = 12 * MEG;   // fp16(W1^T)          [2048 x 2048]
constexpr size_t OFF_A2 = 16 * MEG;   // fp16(W2^T)          [2048 x 2048]
constexpr size_t OFF_P1 = 20 * MEG;   // P1 = W0*W1          [2048 x 2048]
constexpr size_t OFF_Q  = 24 * MEG;   // Q  = (W0*W1*W2)^T   [2048 x 2048]
constexpr size_t POOL   = 28 * MEG;

__device__ __half g_H[POOL];          // fp16 planes

// ---------------- helpers ----------------
DI uint32_t s2u(const void* p) {
    uint32_t r;
    asm("{ .reg .u64 t; cvta.to.shared.u64 t, %1; cvt.u32.u64 %0, t; }" : "=r"(r) : "l"(p));
    return r;
}
DI void cp16(uint32_t dst, const void* src) {
    asm volatile(
        "{ .reg .u64 g; cvta.to.global.u64 g, %1; cp.async.cg.shared.global [%0], [g], 16; }"
        :: "r"(dst), "l"(src) : "memory");
}
DI void cp_commit() { asm volatile("cp.async.commit_group;" ::: "memory"); }
DI void cp_wait1()  { asm volatile("cp.async.wait_group 1;" ::: "memory"); }

#define LDM4(R0, R1, R2, R3, ADDR) \
    asm volatile("ldmatrix.sync.aligned.m8n8.x4.shared.b16 {%0,%1,%2,%3}, [%4];" \
                 : "=r"(R0), "=r"(R1), "=r"(R2), "=r"(R3) : "r"(ADDR))

#define MMA(C, A, B0, B1) \
    asm volatile("mma.sync.aligned.m16n8k16.row.col.f32.f16.f16.f32 " \
                 "{%0,%1,%2,%3},{%4,%5,%6,%7},{%8,%9},{%0,%1,%2,%3};" \
                 : "+f"((C)[0]), "+f"((C)[1]), "+f"((C)[2]), "+f"((C)[3]) \
                 : "r"((A)[0]), "r"((A)[1]), "r"((A)[2]), "r"((A)[3]), "r"(B0), "r"(B1))

// ============ fused prologue: all packing in ONE kernel ============
__global__ void pack_all_kernel(const float* __restrict__ x0, const float* __restrict__ x1,
                                const float* __restrict__ W0, const float* __restrict__ W1,
                                const float* __restrict__ W2) {
    __shared__ float s[32][33];
    int b = blockIdx.x, tid = threadIdx.x;
    if (b < 12288) {
        const float* src;
        size_t off;
        if (b < 8192) {
            int id = b * 256 + tid;
            int m = id >> 9;
            int c4 = (id & 511) * 4;
            src = (c4 < 1024) ? (x0 + (size_t)m * 1024 + c4)
                              : (x1 + (size_t)m * 1024 + (c4 - 1024));
            off = OFF_X + (size_t)m * KDIM + c4;
        } else {
            int id = (b - 8192) * 256 + tid;
            int m = id >> 9;
            int c4 = (id & 511) * 4;
            src = W0 + (size_t)m * KDIM + c4;
            off = OFF_A0 + (size_t)m * KDIM + c4;
        }
        float4 v = *(const float4*)src;
        *(__half2*)(&g_H[off])     = __halves2half2(__float2half_rn(v.x), __float2half_rn(v.y));
        *(__half2*)(&g_H[off + 2]) = __halves2half2(__float2half_rn(v.z), __float2half_rn(v.w));
    } else {
        const float* W = (b < 16384) ? W1 : W2;
        size_t dstoff = (b < 16384) ? OFF_B1 : OFF_A2;
        int bb = (b < 16384) ? (b - 12288) : (b - 16384);
        int n0 = (bb & 63) * 32, k0 = (bb >> 6) * 32;
        int tx = tid & 31, ty = tid >> 5;     // (32, 8)
#pragma unroll
        for (int i = 0; i < 4; i++)
            s[ty + i * 8][tx] = W[(size_t)(k0 + ty + i * 8) * KDIM + n0 + tx];
        __syncthreads();
#pragma unroll
        for (int i = 0; i < 4; i++) {
            float v = s[tx][ty + i * 8];      // (k_local=tx, n_local=ty+8i)
            size_t off = dstoff + (size_t)(n0 + ty + i * 8) * KDIM + k0 + tx;
            g_H[off] = __float2half_rn(v);
        }
    }
}

// ============ main GEMM: C = Ah @ Bh^T (plain fp16, fp32 accumulate) ============
// CTA tile 64x128, warp grid 2x4, warp tile 32x32.
// TWO k-chunks per wait/sync (halved barrier frequency), 6-stage smem ring.
template <bool PACK, int MSHIFT>
__global__ void __launch_bounds__(256, 2)
gemm_kernel(size_t aoff, size_t boff, size_t ooff, float* __restrict__ out) {
    extern __shared__ uint8_t smem[];
    uint32_t tiles = (s2u(smem) + 127u) & ~127u;

    const __half* Ah = g_H + aoff;
    const __half* Bh = g_H + boff;
    __half* Oh = g_H + ooff;

    int tid = threadIdx.x, lane = tid & 31, wid = tid >> 5;
    int warp_m = wid >> 2, warp_n = wid & 3;            // 2 x 4 warp grid, 32x32 tiles
    int mtile = blockIdx.x & ((1 << MSHIFT) - 1), ntile = blockIdx.x >> MSHIFT;

    const size_t arow = (size_t)mtile * BM * KDIM;
    const size_t brow = (size_t)ntile * BN * KDIM;

    float c[2][4][4];
#pragma unroll
    for (int a = 0; a < 2; a++)
#pragma unroll
        for (int b = 0; b < 4; b++)
#pragma unroll
            for (int d = 0; d < 4; d++) c[a][b][d] = 0.f;

    // per-chunk loader (no commit): A (64 rows) + B (128 rows), 64B/row, swizzled
    const int lr = tid >> 2;         // 0..63
    const int cc = tid & 3;
    auto load_chunk = [&](int chunk) {
        if (chunk < NK) {
            uint32_t st = tiles + (uint32_t)(chunk % STAGES) * STAGE_BYTES;
            const size_t gofs = (size_t)chunk * BK + cc * 8;
            uint32_t sw = (uint32_t)((cc ^ ((lr >> 1) & 3)) << 4);
            uint32_t rowb = (uint32_t)lr * 64u;
            cp16(st + rowb + sw, Ah + arow + (size_t)lr * KDIM + gofs);
            cp16(st + APLANE + rowb + sw, Bh + brow + (size_t)lr * KDIM + gofs);
            int r2 = lr + 64;
            uint32_t sw2 = (uint32_t)((cc ^ ((r2 >> 1) & 3)) << 4);
            uint32_t rowb2 = (uint32_t)r2 * 64u;
            cp16(st + APLANE + rowb2 + sw2, Bh + brow + (size_t)r2 * KDIM + gofs);
        }
    };

    // prologue: chunks {0,1} -> group0, {2,3} -> group1
    load_chunk(0); load_chunk(1); cp_commit();
    load_chunk(2); load_chunk(3); cp_commit();

    // ldmatrix lane->row/chunk mapping (m16n8k16 fragment layouts)
    const int aR = warp_m * 32 + (lane & 7) + ((lane >> 3) & 1) * 8;
    const int aC = lane >> 4;
    const int bR = warp_n * 32 + (lane & 7) + ((lane >> 4) << 3);
    const int bC = (lane >> 3) & 1;

    // double-buffered fragments (per half-chunk)
    uint32_t ahf[2][2][4], bhf[2][4][2];

    auto ldfrags = [&](int buf, uint32_t st, int ks) {
#pragma unroll
        for (int tm = 0; tm < 2; tm++) {
            int row = aR + tm * 16;
            uint32_t cidx = (uint32_t)((ks * 2 + aC) ^ ((row >> 1) & 3));
            uint32_t ad = st + (uint32_t)row * 64u + (cidx << 4);
            LDM4(ahf[buf][tm][0], ahf[buf][tm][1], ahf[buf][tm][2], ahf[buf][tm][3], ad);
        }
#pragma unroll
        for (int p = 0; p < 2; p++) {
            int row = bR + p * 16;
            uint32_t cidx = (uint32_t)((ks * 2 + bC) ^ ((row >> 1) & 3));
            uint32_t bd = st + APLANE + (uint32_t)row * 64u + (cidx << 4);
            uint32_t r0, r1, r2, r3;
            LDM4(r0, r1, r2, r3, bd);
            bhf[buf][2 * p][0] = r0; bhf[buf][2 * p][1] = r1;
            bhf[buf][2 * p + 1][0] = r2; bhf[buf][2 * p + 1][1] = r3;
        }
    };

    auto mma_pass = [&](int buf) {
#pragma unroll
        for (int tm = 0; tm < 2; tm++)
#pragma unroll
            for (int tn = 0; tn < 4; tn++)
                MMA(c[tm][tn], ahf[buf][tm], bhf[buf][tn][0], bhf[buf][tn][1]);
    };

    // main loop: 2 chunks (4 half-chunks, 32 warp-MMAs) per wait+sync
#pragma unroll 1
    for (int kk = 0; kk < NK; kk += 2) {
        cp_wait1();                       // group kk/2 done: chunks kk, kk+1 arrived
        __syncthreads();                  // visibility + stages (kk+4)%6,(kk+5)%6 free
        load_chunk(kk + 4); load_chunk(kk + 5); cp_commit();
        uint32_t st0 = tiles + (uint32_t)(kk % STAGES) * STAGE_BYTES;
        uint32_t st1 = tiles + (uint32_t)((kk + 1) % STAGES) * STAGE_BYTES;
        ldfrags(0, st0, 0);
        ldfrags(1, st0, 1);               // overlaps mma below
        mma_pass(0);                      // (kk, half 0)
        ldfrags(0, st1, 0);               // overlaps mma below
        mma_pass(1);                      // (kk, half 1)
        ldfrags(1, st1, 1);               // overlaps mma below
        mma_pass(0);                      // (kk+1, half 0)
        mma_pass(1);                      // (kk+1, half 1)
    }

    // ---- epilogue ----
    int r0 = mtile * BM + warp_m * 32 + (lane >> 2);
    int col0 = ntile * BN + warp_n * 32 + (lane & 3) * 2;
#pragma unroll
    for (int tm = 0; tm < 2; tm++)
#pragma unroll
        for (int tn = 0; tn < 4; tn++) {
            int r = r0 + tm * 16, ccc = col0 + tn * 8;
            float* v = c[tm][tn];
            if (PACK) {
#pragma unroll
                for (int h = 0; h < 2; h++) {
                    size_t off = (size_t)(r + h * 8) * KDIM + ccc;
                    *(__half2*)(Oh + off) =
                        __halves2half2(__float2half_rn(v[2 * h]), __float2half_rn(v[2 * h + 1]));
                }
            } else {
                *(float2*)(out + (size_t)r * KDIM + ccc) = make_float2(v[0], v[1]);
                *(float2*)(out + (size_t)(r + 8) * KDIM + ccc) = make_float2(v[2], v[3]);
            }
        }
}

// ---------------- launch ----------------
// out = X * (W0*W1*W2), all GEMMs plain fp16 with fp32 accumulate:
//   P1 = fp16(W0) * fp16(W1^T)^T
//   Q  = (P1*W2)^T : Q[j][t2] = sum_t W2^T[j][t]*P1[t2][t]
//   out[i][j] = sum_k fp16(X)[i][k]*Q[j][k]
extern "C" void kernel_launch(void* const* d_in, const int* in_sizes, int n_in,
                              void* d_out, int out_size) {
    const float* x0 = (const float*)d_in[0];
    const float* x1 = (const float*)d_in[1];
    const float* W0 = (const float*)d_in[2];
    const float* W1 = (const float*)d_in[3];
    const float* W2 = (const float*)d_in[4];
    float* out = (float*)d_out;

    cudaFuncSetAttribute(gemm_kernel<true, 5>,
                         cudaFuncAttributeMaxDynamicSharedMemorySize, SMEM_DYN);
    cudaFuncSetAttribute(gemm_kernel<false, 6>,
                         cudaFuncAttributeMaxDynamicSharedMemorySize, SMEM_DYN);

    pack_all_kernel<<<20480, 256>>>(x0, x1, W0, W1, W2);
    // weight GEMMs: 32 mtiles x 16 ntiles = 512 CTAs
    gemm_kernel<true, 5><<<32 * 16, 256, SMEM_DYN>>>(OFF_A0, OFF_B1, OFF_P1, nullptr);
    gemm_kernel<true, 5><<<32 * 16, 256, SMEM_DYN>>>(OFF_A2, OFF_P1, OFF_Q, nullptr);
    // final GEMM: 64 mtiles x 16 ntiles = 1024 CTAs
    gemm_kernel<false, 6><<<64 * 16, 256, SMEM_DYN>>>(OFF_X, OFF_Q, 0, out);
}

// round 17
// speedup vs baseline: 1.2528x; 1.2528x over previous
#include <cuda_runtime.h>
#include <cuda_fp16.h>
#include <cstdint>
#include <cstddef>

#define DI __device__ __forceinline__

// ---------------- problem constants ----------------
constexpr int KDIM  = 2048;           // K == N for every GEMM
constexpr int BM = 64, BN = 256, BK = 32;
constexpr int NK = KDIM / BK;         // 64 k-chunks
constexpr int STAGES = 4;
constexpr uint32_t APLANE = BM * 64u;                 // 4096 B
constexpr uint32_t BPLANE = BN * 64u;                 // 16384 B
constexpr uint32_t STAGE_BYTES = APLANE + BPLANE;     // 20480
constexpr uint32_t SMEM_DYN = STAGES * STAGE_BYTES + 128;   // ~82KB -> 2 CTAs/SM

// ---------------- plane pool (all tensors single fp16 plane) ----------------
constexpr size_t MEG = 1024ull * 1024ull;
constexpr size_t OFF_X  = 0;          // fp16(concat(x0,x1)) [4096 x 2048]
constexpr size_t OFF_A0 = 8 * MEG;    // fp16(W0) row-major  [2048 x 2048]
constexpr size_t OFF_B1 = 12 * MEG;   // fp16(W1^T)          [2048 x 2048]
constexpr size_t OFF_A2 = 16 * MEG;   // fp16(W2^T)          [2048 x 2048]
constexpr size_t OFF_P1 = 20 * MEG;   // P1 = W0*W1          [2048 x 2048]
constexpr size_t OFF_Q  = 24 * MEG;   // Q  = (W0*W1*W2)^T   [2048 x 2048]
constexpr size_t POOL   = 28 * MEG;

__device__ __half g_H[POOL];          // fp16 planes

// ---------------- helpers ----------------
DI uint32_t s2u(const void* p) {
    uint32_t r;
    asm("{ .reg .u64 t; cvta.to.shared.u64 t, %1; cvt.u32.u64 %0, t; }" : "=r"(r) : "l"(p));
    return r;
}
DI void cp16(uint32_t dst, const void* src) {
    asm volatile(
        "{ .reg .u64 g; cvta.to.global.u64 g, %1; cp.async.cg.shared.global [%0], [g], 16; }"
        :: "r"(dst), "l"(src) : "memory");
}
DI void cp_commit() { asm volatile("cp.async.commit_group;" ::: "memory"); }
DI void cp_wait1()  { asm volatile("cp.async.wait_group 1;" ::: "memory"); }
DI void cp_wait2()  { asm volatile("cp.async.wait_group 2;" ::: "memory"); }

#define LDM4(R0, R1, R2, R3, ADDR) \
    asm volatile("ldmatrix.sync.aligned.m8n8.x4.shared.b16 {%0,%1,%2,%3}, [%4];" \
                 : "=r"(R0), "=r"(R1), "=r"(R2), "=r"(R3) : "r"(ADDR))

#define MMA(C, A, B0, B1) \
    asm volatile("mma.sync.aligned.m16n8k16.row.col.f32.f16.f16.f32 " \
                 "{%0,%1,%2,%3},{%4,%5,%6,%7},{%8,%9},{%0,%1,%2,%3};" \
                 : "+f"((C)[0]), "+f"((C)[1]), "+f"((C)[2]), "+f"((C)[3]) \
                 : "r"((A)[0]), "r"((A)[1]), "r"((A)[2]), "r"((A)[3]), "r"(B0), "r"(B1))

// ============ fused prologue: all packing in ONE kernel ============
__global__ void pack_all_kernel(const float* __restrict__ x0, const float* __restrict__ x1,
                                const float* __restrict__ W0, const float* __restrict__ W1,
                                const float* __restrict__ W2) {
    __shared__ float s[32][33];
    int b = blockIdx.x, tid = threadIdx.x;
    if (b < 12288) {
        const float* src;
        size_t off;
        if (b < 8192) {
            int id = b * 256 + tid;
            int m = id >> 9;
            int c4 = (id & 511) * 4;
            src = (c4 < 1024) ? (x0 + (size_t)m * 1024 + c4)
                              : (x1 + (size_t)m * 1024 + (c4 - 1024));
            off = OFF_X + (size_t)m * KDIM + c4;
        } else {
            int id = (b - 8192) * 256 + tid;
            int m = id >> 9;
            int c4 = (id & 511) * 4;
            src = W0 + (size_t)m * KDIM + c4;
            off = OFF_A0 + (size_t)m * KDIM + c4;
        }
        float4 v = *(const float4*)src;
        *(__half2*)(&g_H[off])     = __halves2half2(__float2half_rn(v.x), __float2half_rn(v.y));
        *(__half2*)(&g_H[off + 2]) = __halves2half2(__float2half_rn(v.z), __float2half_rn(v.w));
    } else {
        const float* W = (b < 16384) ? W1 : W2;
        size_t dstoff = (b < 16384) ? OFF_B1 : OFF_A2;
        int bb = (b < 16384) ? (b - 12288) : (b - 16384);
        int n0 = (bb & 63) * 32, k0 = (bb >> 6) * 32;
        int tx = tid & 31, ty = tid >> 5;     // (32, 8)
#pragma unroll
        for (int i = 0; i < 4; i++)
            s[ty + i * 8][tx] = W[(size_t)(k0 + ty + i * 8) * KDIM + n0 + tx];
        __syncthreads();
#pragma unroll
        for (int i = 0; i < 4; i++) {
            float v = s[tx][ty + i * 8];      // (k_local=tx, n_local=ty+8i)
            size_t off = dstoff + (size_t)(n0 + ty + i * 8) * KDIM + k0 + tx;
            g_H[off] = __float2half_rn(v);
        }
    }
}

// ============ main GEMM: C = Ah @ Bh^T (plain fp16, fp32 accumulate) ============
// CTA tile 64x256, warp grid 2x4, warp tile 32x64. (round-14 mainloop, unchanged)
// moff: mtile offset (in BM units) — lets the caller split M into single-wave launches.
template <bool PACK, int MSHIFT>
__global__ void __launch_bounds__(256, 2)
gemm_kernel(size_t aoff, size_t boff, size_t ooff, int moff, float* __restrict__ out) {
    extern __shared__ uint8_t smem[];
    uint32_t tiles = (s2u(smem) + 127u) & ~127u;

    const __half* Ah = g_H + aoff;
    const __half* Bh = g_H + boff;
    __half* Oh = g_H + ooff;

    int tid = threadIdx.x, lane = tid & 31, wid = tid >> 5;
    int warp_m = wid >> 2, warp_n = wid & 3;            // 2 x 4 warp grid, 32x64 tiles
    int mtile = (blockIdx.x & ((1 << MSHIFT) - 1)) + moff, ntile = blockIdx.x >> MSHIFT;

    const size_t arow = (size_t)mtile * BM * KDIM;
    const size_t brow = (size_t)ntile * BN * KDIM;

    float c[2][8][4];
#pragma unroll
    for (int a = 0; a < 2; a++)
#pragma unroll
        for (int b = 0; b < 8; b++)
#pragma unroll
            for (int d = 0; d < 4; d++) c[a][b][d] = 0.f;

    // per-chunk loader: A (64 rows) + B (256 rows), 64B/row, swizzled 16B chunks
    const int lr = tid >> 2;         // 0..63
    const int cc = tid & 3;
    auto load_chunk = [&](int chunk) {
        if (chunk < NK) {
            uint32_t st = tiles + (uint32_t)(chunk % STAGES) * STAGE_BYTES;
            const size_t gofs = (size_t)chunk * BK + cc * 8;
            uint32_t sw = (uint32_t)((cc ^ ((lr >> 1) & 3)) << 4);
            cp16(st + (uint32_t)lr * 64u + sw, Ah + arow + (size_t)lr * KDIM + gofs);
#pragma unroll
            for (int j = 0; j < 4; j++) {
                int r2 = lr + j * 64;
                uint32_t sw2 = (uint32_t)((cc ^ ((r2 >> 1) & 3)) << 4);
                cp16(st + APLANE + (uint32_t)r2 * 64u + sw2,
                     Bh + brow + (size_t)r2 * KDIM + gofs);
            }
        }
        cp_commit();
    };

#pragma unroll
    for (int c0 = 0; c0 < STAGES - 1; c0++) load_chunk(c0);

    // ldmatrix lane->row/chunk mapping (m16n8k16 fragment layouts)
    const int aR = warp_m * 32 + (lane & 7) + ((lane >> 3) & 1) * 8;
    const int aC = lane >> 4;
    const int bR = warp_n * 64 + (lane & 7) + ((lane >> 4) << 3);
    const int bC = (lane >> 3) & 1;

    // double-buffered fragments
    uint32_t ahf[2][2][4], bhf[2][8][2];

    auto ldfrags = [&](int buf, uint32_t st, int ks) {
#pragma unroll
        for (int tm = 0; tm < 2; tm++) {
            int row = aR + tm * 16;
            uint32_t cidx = (uint32_t)((ks * 2 + aC) ^ ((row >> 1) & 3));
            uint32_t ad = st + (uint32_t)row * 64u + (cidx << 4);
            LDM4(ahf[buf][tm][0], ahf[buf][tm][1], ahf[buf][tm][2], ahf[buf][tm][3], ad);
        }
#pragma unroll
        for (int p = 0; p < 4; p++) {
            int row = bR + p * 16;
            uint32_t cidx = (uint32_t)((ks * 2 + bC) ^ ((row >> 1) & 3));
            uint32_t bd = st + APLANE + (uint32_t)row * 64u + (cidx << 4);
            uint32_t r0, r1, r2, r3;
            LDM4(r0, r1, r2, r3, bd);
            bhf[buf][2 * p][0] = r0; bhf[buf][2 * p][1] = r1;
            bhf[buf][2 * p + 1][0] = r2; bhf[buf][2 * p + 1][1] = r3;
        }
    };

    auto mma_pass = [&](int buf) {
#pragma unroll
        for (int tm = 0; tm < 2; tm++)
#pragma unroll
            for (int tn = 0; tn < 8; tn++)
                MMA(c[tm][tn], ahf[buf][tm], bhf[buf][tn][0], bhf[buf][tn][1]);
    };

    cp_wait2();             // chunk 0 arrived (3 groups committed, <=2 pending)
    __syncthreads();
    ldfrags(0, tiles, 0);   // chunk 0, ks=0

#pragma unroll 1
    for (int k = 0; k < NK; k++) {
        uint32_t st = tiles + (uint32_t)(k % STAGES) * STAGE_BYTES;
        ldfrags(1, st, 1);              // ks=1 frags: overlaps with buf0 MMAs below
        mma_pass(0);
        cp_wait1();                     // chunk k+1 arrived
        __syncthreads();                // all warps done reading chunk k-1 stage
        load_chunk(k + STAGES - 1);     // refill stage (k-1)%4 with chunk k+3
        if (k + 1 < NK) {
            uint32_t st2 = tiles + (uint32_t)((k + 1) % STAGES) * STAGE_BYTES;
            ldfrags(0, st2, 0);         // prefetch next chunk ks=0: overlaps buf1 MMAs
        }
        mma_pass(1);
    }

    // ---- epilogue ----
    int r0 = mtile * BM + warp_m * 32 + (lane >> 2);
    int col0 = ntile * BN + warp_n * 64 + (lane & 3) * 2;
#pragma unroll
    for (int tm = 0; tm < 2; tm++)
#pragma unroll
        for (int tn = 0; tn < 8; tn++) {
            int r = r0 + tm * 16, ccc = col0 + tn * 8;
            float* v = c[tm][tn];
            if (PACK) {
#pragma unroll
                for (int h = 0; h < 2; h++) {
                    size_t off = (size_t)(r + h * 8) * KDIM + ccc;
                    *(__half2*)(Oh + off) =
                        __halves2half2(__float2half_rn(v[2 * h]), __float2half_rn(v[2 * h + 1]));
                }
            } else {
                *(float2*)(out + (size_t)r * KDIM + ccc) = make_float2(v[0], v[1]);
                *(float2*)(out + (size_t)(r + 8) * KDIM + ccc) = make_float2(v[2], v[3]);
            }
        }
}

// ---------------- launch ----------------
// out = X * (W0*W1*W2), all GEMMs plain fp16 with fp32 accumulate:
//   P1 = fp16(W0) * fp16(W1^T)^T
//   Q  = (P1*W2)^T : Q[j][t2] = sum_t W2^T[j][t]*P1[t2][t]
//   out[i][j] = sum_k fp16(X)[i][k]*Q[j][k]
// The final GEMM is split into two single-wave 256-CTA launches (M halves):
// measured single-wave launches run ~1.10x of floor vs ~1.41x for 2-wave.
extern "C" void kernel_launch(void* const* d_in, const int* in_sizes, int n_in,
                              void* d_out, int out_size) {
    const float* x0 = (const float*)d_in[0];
    const float* x1 = (const float*)d_in[1];
    const float* W0 = (const float*)d_in[2];
    const float* W1 = (const float*)d_in[3];
    const float* W2 = (const float*)d_in[4];
    float* out = (float*)d_out;

    cudaFuncSetAttribute(gemm_kernel<true, 5>,
                         cudaFuncAttributeMaxDynamicSharedMemorySize, SMEM_DYN);
    cudaFuncSetAttribute(gemm_kernel<false, 5>,
                         cudaFuncAttributeMaxDynamicSharedMemorySize, SMEM_DYN);

    pack_all_kernel<<<20480, 256>>>(x0, x1, W0, W1, W2);
    // weight GEMMs: 32 mtiles x 8 ntiles = 256 CTAs (single wave at occ 2)
    gemm_kernel<true, 5><<<32 * 8, 256, SMEM_DYN>>>(OFF_A0, OFF_B1, OFF_P1, 0, nullptr);
    gemm_kernel<true, 5><<<32 * 8, 256, SMEM_DYN>>>(OFF_A2, OFF_P1, OFF_Q, 0, nullptr);
    // final GEMM: two single-wave launches over M halves (32 mtiles each)
    gemm_kernel<false, 5><<<32 * 8, 256, SMEM_DYN>>>(OFF_X, OFF_Q, 0, 0, out);
    gemm_kernel<false, 5><<<32 * 8, 256, SMEM_DYN>>>(OFF_X, OFF_Q, 0, 32, out);
}